// round 1
// baseline (speedup 1.0000x reference)
#include <cuda_runtime.h>
#include <cstdint>

// Problem shape (fixed by the dataset): B=256 batches of N=512 x 512 binary adjacency.
constexpr int B = 256;
constexpr int N = 512;
constexpr int W = N / 32;  // 16 uint32 words per bit-packed row

// Scratch (allocation-free rule: __device__ globals).
__device__ unsigned g_bits[(size_t)B * N * W];  // 8 MB bit-packed adjacency_hat
__device__ float    g_dis [(size_t)B * N];      // 512 KB d_inv_sqrt

// ---------------------------------------------------------------------------
// Pass 1: one warp per row. Read the 2KB float row once (16 coalesced 128B
// iterations), ballot-pack it to 512 bits, warp-reduce the degree, patch the
// diagonal with the atom mask, emit d^-1/2 and the packed row.
// ---------------------------------------------------------------------------
__global__ void __launch_bounds__(256) degree_pack_kernel(const float* __restrict__ adj) {
    const int row  = blockIdx.x * (blockDim.x >> 5) + (threadIdx.x >> 5);  // 0 .. B*N-1
    const int lane = threadIdx.x & 31;

    const float* rp = adj + (size_t)row * N;

    float acc = 0.0f;
    unsigned myword = 0;  // lane t (t<16) ends up owning bit-word t
    #pragma unroll
    for (int t = 0; t < W; t++) {
        float v = rp[t * 32 + lane];                        // coalesced 128B
        unsigned bal = __ballot_sync(0xffffffffu, v != 0.0f);
        if (lane == t) myword = bal;
        acc += v;                                           // entries are 0/1 -> exact
    }

    // Warp-reduce the row sum.
    #pragma unroll
    for (int o = 16; o; o >>= 1) acc += __shfl_xor_sync(0xffffffffu, acc, o);

    const int i  = row & (N - 1);   // row index within the batch
    const int dw = i >> 5;          // word holding the diagonal bit
    const int db = i & 31;

    const unsigned diagword = __shfl_sync(0xffffffffu, myword, dw);
    const float diagv = (float)((diagword >> db) & 1u);

    const unsigned mask  = (acc != 0.0f) ? 1u : 0u;     // atom_mask
    const float    maskf = (float)mask;

    // degree_hat = rowsum - old_diag + mask
    const float degree = acc - diagv + maskf;

    // Patch diagonal bit to the mask value.
    if (lane == dw) myword = (myword & ~(1u << db)) | (mask << db);

    if (lane < W) g_bits[(size_t)row * W + lane] = myword;   // 64B per warp
    if (lane == 0) g_dis[row] = (degree > 0.0f) ? rsqrtf(degree) : 0.0f;
}

// ---------------------------------------------------------------------------
// Pass 2: out[b,i,j] = dis[b,i] * dis[b,j] * bit(b,i,j).
// One block per 16 output rows of one batch; dis vector staged in smem.
// Each warp emits one 2KB row via 4 x STG.128 per lane.
// ---------------------------------------------------------------------------
__global__ void __launch_bounds__(512) scale_kernel(float* __restrict__ out) {
    __shared__ float s_dis[N];

    const int batch  = blockIdx.x >> 5;   // 32 blocks per batch
    const int rowblk = blockIdx.x & 31;   // 16 rows each
    const int tid    = threadIdx.x;       // 512 threads

    s_dis[tid] = g_dis[(size_t)batch * N + tid];
    __syncthreads();

    const int wid  = tid >> 5;
    const int lane = tid & 31;
    const int i    = rowblk * 16 + wid;

    const float dis_i = s_dis[i];

    const unsigned* wp = g_bits + ((size_t)batch * N + i) * W;
    const unsigned myw = (lane < W) ? wp[lane] : 0u;  // lane l holds word l

    float4* orow = reinterpret_cast<float4*>(out + ((size_t)batch * N + i) * N);
    const float4* s4 = reinterpret_cast<const float4*>(s_dis);

    #pragma unroll
    for (int c = 0; c < 4; c++) {
        // float4 index f = c*32 + lane  ->  j = 4f; bit-word = j/32 = c*4 + lane/8
        const unsigned w   = __shfl_sync(0xffffffffu, myw, c * 4 + (lane >> 3));
        const unsigned nib = (w >> ((lane & 7) * 4)) & 0xFu;

        const float4 d = s4[c * 32 + lane];
        float4 v;
        v.x = (nib & 1u) ? dis_i * d.x : 0.0f;
        v.y = (nib & 2u) ? dis_i * d.y : 0.0f;
        v.z = (nib & 4u) ? dis_i * d.z : 0.0f;
        v.w = (nib & 8u) ? dis_i * d.w : 0.0f;
        orow[c * 32 + lane] = v;  // STG.128, coalesced
    }
}

extern "C" void kernel_launch(void* const* d_in, const int* in_sizes, int n_in,
                              void* d_out, int out_size) {
    const float* adj = (const float*)d_in[0];
    float* out = (float*)d_out;
    (void)in_sizes; (void)n_in; (void)out_size;

    // Pass 1: one warp per row, 8 warps per block -> B*N/8 blocks.
    degree_pack_kernel<<<(B * N) / 8, 256>>>(adj);
    // Pass 2: 32 blocks per batch, 512 threads.
    scale_kernel<<<B * 32, 512>>>(out);
}

// round 2
// speedup vs baseline: 1.0256x; 1.0256x over previous
#include <cuda_runtime.h>
#include <cstdint>

// Problem shape (fixed by the dataset): B=256 batches of N=512 x 512 binary adjacency.
constexpr int B = 256;
constexpr int N = 512;
constexpr int W = N / 32;   // 16 uint32 words per bit-packed row
constexpr int F4 = N / 4;   // 128 float4 per row

// Fused kernel: one CTA per batch (1024 threads = 32 warps).
//  Phase A: read the 1MB batch once (LDG.128 streaming), bit-pack each row into
//           shared memory (32KB) and compute integer row degrees via POPC.
//  Mid:     per-row diagonal patch + d^-1/2 into shared.
//  Phase B: reconstruct out[i][j] = dis[i]*dis[j]*bit(i,j) from smem, STG.128.
__global__ void __launch_bounds__(1024, 2)
fused_normalize_kernel(const float* __restrict__ adj, float* __restrict__ out) {
    __shared__ unsigned s_bits[N * W];  // 32 KB packed adjacency (pre-patch raw, then patched)
    __shared__ int      s_deg[N];       // raw row sums
    __shared__ float    s_dis[N];       // d^-1/2

    const int batch = blockIdx.x;
    const int tid   = threadIdx.x;
    const int wid   = tid >> 5;
    const int lane  = tid & 31;
    const int sub   = lane & 7;   // position within 8-lane word group
    const int grp   = lane >> 3;  // which of 4 word groups

    const float4* a4 = reinterpret_cast<const float4*>(adj) + (size_t)batch * N * F4;

    // ---- Phase A: each warp packs 16 consecutive rows ----
    #pragma unroll 1
    for (int k = 0; k < 16; k++) {
        const int row = wid * 16 + k;
        const float4* r4 = a4 + (size_t)row * F4;

        // 4 independent 128-bit streaming loads (512 floats / warp-row)
        float4 v[4];
        #pragma unroll
        for (int c = 0; c < 4; c++) v[c] = __ldcs(&r4[c * 32 + lane]);

        int cnt = 0;
        #pragma unroll
        for (int c = 0; c < 4; c++) {
            unsigned nib = (v[c].x != 0.0f ? 1u : 0u) |
                           (v[c].y != 0.0f ? 2u : 0u) |
                           (v[c].z != 0.0f ? 4u : 0u) |
                           (v[c].w != 0.0f ? 8u : 0u);
            cnt += __popc(nib);
            unsigned part = nib << (sub * 4);
            // OR-reduce within each 8-lane group -> full 32-bit word
            part |= __shfl_xor_sync(0xffffffffu, part, 1);
            part |= __shfl_xor_sync(0xffffffffu, part, 2);
            part |= __shfl_xor_sync(0xffffffffu, part, 4);
            if (sub == 0) s_bits[row * W + c * 4 + grp] = part;
        }
        // warp-reduce the integer degree
        #pragma unroll
        for (int o = 16; o; o >>= 1) cnt += __shfl_xor_sync(0xffffffffu, cnt, o);
        if (lane == 0) s_deg[row] = cnt;
    }
    __syncthreads();

    // ---- Mid: diagonal patch + d^-1/2 (one thread per row) ----
    if (tid < N) {
        const int i  = tid;
        const int dw = i >> 5, db = i & 31;
        unsigned wrd = s_bits[i * W + dw];
        const int diag = (wrd >> db) & 1;
        const int cnt  = s_deg[i];
        const int mask = (cnt != 0) ? 1 : 0;          // atom_mask
        const int deg  = cnt - diag + mask;           // degree_hat
        s_dis[i] = (deg > 0) ? rsqrtf((float)deg) : 0.0f;
        if (diag != mask)
            s_bits[i * W + dw] = (wrd & ~(1u << db)) | ((unsigned)mask << db);
    }
    __syncthreads();

    // ---- Phase B: each warp emits 16 rows, STG.128 streaming ----
    const float4* d4 = reinterpret_cast<const float4*>(s_dis);
    float4* o4 = reinterpret_cast<float4*>(out) + (size_t)batch * N * F4;

    #pragma unroll 1
    for (int k = 0; k < 16; k++) {
        const int i = wid * 16 + k;
        const float di = s_dis[i];
        float4* orow = o4 + (size_t)i * F4;
        #pragma unroll
        for (int c = 0; c < 4; c++) {
            const unsigned w   = s_bits[i * W + c * 4 + grp];  // 8-lane broadcast, no conflict
            const unsigned nib = (w >> (sub * 4)) & 0xFu;
            const float4 d = d4[c * 32 + lane];
            float4 v;
            v.x = (nib & 1u) ? di * d.x : 0.0f;
            v.y = (nib & 2u) ? di * d.y : 0.0f;
            v.z = (nib & 4u) ? di * d.z : 0.0f;
            v.w = (nib & 8u) ? di * d.w : 0.0f;
            __stcs(&orow[c * 32 + lane], v);  // coalesced 512B per warp per c
        }
    }
}

extern "C" void kernel_launch(void* const* d_in, const int* in_sizes, int n_in,
                              void* d_out, int out_size) {
    const float* adj = (const float*)d_in[0];
    float* out = (float*)d_out;
    (void)in_sizes; (void)n_in; (void)out_size;

    fused_normalize_kernel<<<B, 1024>>>(adj, out);
}

// round 3
// speedup vs baseline: 1.0745x; 1.0477x over previous
#include <cuda_runtime.h>
#include <cstdint>

// B=256 batches of N=512 x 512 binary (0/1) float32 adjacency.
constexpr int B  = 256;
constexpr int N  = 512;
constexpr int W  = N / 32;   // 16 packed words per row
constexpr int WS = W + 1;    // padded stride 17 (odd -> conflict-free column reads)
constexpr int F4 = N / 4;    // 128 float4 per row

// One CTA per batch, 512 threads = 16 warps; each warp owns 32 rows.
__global__ void __launch_bounds__(512)
fused_normalize_kernel(const float* __restrict__ adj, float* __restrict__ out) {
    __shared__ unsigned s_bits[N * WS];  // ~34.8 KB packed adjacency (padded)
    __shared__ float    s_dis[N];        // d^-1/2

    const int batch = blockIdx.x;
    const int tid   = threadIdx.x;
    const int wid   = tid >> 5;      // 0..15
    const int lane  = tid & 31;
    const int sub   = lane & 7;      // position within 8-lane word group
    const int grp   = lane >> 3;     // which of 4 word groups

    const float4* a4 = reinterpret_cast<const float4*>(adj) + (size_t)batch * N * F4;

    // ---- Phase A: pack 2 rows per iteration (8 independent LDG.128 in flight) ----
    #pragma unroll 1
    for (int k = 0; k < 16; k++) {
        const int r0 = wid * 32 + 2 * k;
        const int r1 = r0 + 1;
        const float4* p0 = a4 + (size_t)r0 * F4;
        const float4* p1 = a4 + (size_t)r1 * F4;

        float4 a[4], b[4];
        #pragma unroll
        for (int c = 0; c < 4; c++) {
            a[c] = __ldcs(&p0[c * 32 + lane]);
            b[c] = __ldcs(&p1[c * 32 + lane]);
        }

        #pragma unroll
        for (int c = 0; c < 4; c++) {
            unsigned nib0 = (a[c].x != 0.0f ? 1u : 0u) | (a[c].y != 0.0f ? 2u : 0u) |
                            (a[c].z != 0.0f ? 4u : 0u) | (a[c].w != 0.0f ? 8u : 0u);
            unsigned nib1 = (b[c].x != 0.0f ? 1u : 0u) | (b[c].y != 0.0f ? 2u : 0u) |
                            (b[c].z != 0.0f ? 4u : 0u) | (b[c].w != 0.0f ? 8u : 0u);
            unsigned p0w = nib0 << (sub * 4);
            unsigned p1w = nib1 << (sub * 4);
            p0w |= __shfl_xor_sync(0xffffffffu, p0w, 1);
            p1w |= __shfl_xor_sync(0xffffffffu, p1w, 1);
            p0w |= __shfl_xor_sync(0xffffffffu, p0w, 2);
            p1w |= __shfl_xor_sync(0xffffffffu, p1w, 2);
            p0w |= __shfl_xor_sync(0xffffffffu, p0w, 4);
            p1w |= __shfl_xor_sync(0xffffffffu, p1w, 4);
            if (sub == 0) {
                s_bits[r0 * WS + c * 4 + grp] = p0w;
                s_bits[r1 * WS + c * 4 + grp] = p1w;
            }
        }
    }
    __syncthreads();

    // ---- Patch: one thread per row. popc the packed row (conflict-free via
    //      odd stride), fix the diagonal, emit d^-1/2. ----
    {
        const int i = tid;  // 512 threads == N rows
        unsigned w[W];
        int cnt = 0;
        #pragma unroll
        for (int t = 0; t < W; t++) {
            w[t] = s_bits[i * WS + t];
            cnt += __popc(w[t]);
        }
        const int dw = i >> 5, db = i & 31;
        const int diag = (w[dw] >> db) & 1;
        const int mask = (cnt != 0) ? 1 : 0;             // atom_mask
        const int deg  = cnt - diag + mask;              // degree_hat
        s_dis[i] = (deg > 0) ? rsqrtf((float)deg) : 0.0f;
        if (diag != mask) s_bits[i * WS + dw] = w[dw] ^ (1u << db);
    }
    __syncthreads();

    // ---- Phase B: out[i][j] = dis[i]*dis[j]*bit(i,j), 2 rows/iter, STG.128 ----
    const float4* d4 = reinterpret_cast<const float4*>(s_dis);
    float4 dreg[4];
    #pragma unroll
    for (int c = 0; c < 4; c++) dreg[c] = d4[c * 32 + lane];  // row-invariant

    float4* o4 = reinterpret_cast<float4*>(out) + (size_t)batch * N * F4;

    #pragma unroll 1
    for (int k = 0; k < 16; k++) {
        const int r0 = wid * 32 + 2 * k;
        const int r1 = r0 + 1;
        const float di0 = s_dis[r0];
        const float di1 = s_dis[r1];
        float4* q0 = o4 + (size_t)r0 * F4;
        float4* q1 = o4 + (size_t)r1 * F4;

        #pragma unroll
        for (int c = 0; c < 4; c++) {
            const unsigned w0 = s_bits[r0 * WS + c * 4 + grp];  // 8-lane broadcast
            const unsigned w1 = s_bits[r1 * WS + c * 4 + grp];
            const unsigned n0 = (w0 >> (sub * 4)) & 0xFu;
            const unsigned n1 = (w1 >> (sub * 4)) & 0xFu;
            const float4 d = dreg[c];
            float4 v0, v1;
            v0.x = (n0 & 1u) ? di0 * d.x : 0.0f;
            v0.y = (n0 & 2u) ? di0 * d.y : 0.0f;
            v0.z = (n0 & 4u) ? di0 * d.z : 0.0f;
            v0.w = (n0 & 8u) ? di0 * d.w : 0.0f;
            v1.x = (n1 & 1u) ? di1 * d.x : 0.0f;
            v1.y = (n1 & 2u) ? di1 * d.y : 0.0f;
            v1.z = (n1 & 4u) ? di1 * d.z : 0.0f;
            v1.w = (n1 & 8u) ? di1 * d.w : 0.0f;
            __stcs(&q0[c * 32 + lane], v0);
            __stcs(&q1[c * 32 + lane], v1);
        }
    }
}

extern "C" void kernel_launch(void* const* d_in, const int* in_sizes, int n_in,
                              void* d_out, int out_size) {
    const float* adj = (const float*)d_in[0];
    float* out = (float*)d_out;
    (void)in_sizes; (void)n_in; (void)out_size;

    fused_normalize_kernel<<<B, 512>>>(adj, out);
}